// round 8
// baseline (speedup 1.0000x reference)
#include <cuda_runtime.h>

// QConv2d: new_rho[b] = U2 @ rho[b] @ U2^T, U2 = uc[:,2:4] ⊗ ux ⊗ uy
// Register-resident separable evaluation; CTA split into FOUR independent
// 64-thread quarter-pipelines (H = left-channel block, h = right-half),
// joined only at P4. Quarter Q = tid>>6, H = Q>>1, h = Q&1.
//
// smem tile A: 128 rows x 132 words (all patterns conflict-free).
// Per quarter (64 threads, named barrier 1+Q):
//   P1q: load rho rows [H*64,+64) x cols [h*64,+64) (coalesced float4)
//   barQ
//   P2q: per-thread row-(h-half) register transform (rows of H block)
//   barQ
//   P3q: per-thread column c = h*64+qtid, rows H block (in-place, own addrs)
// full __syncthreads
//   P4 : fused uc on both sides + coalesced float4 stores.

#define NT 256
#define RS 132
#define A_WORDS (128 * RS)              // 16896
#define SMEM_WORDS (A_WORDS + 4 * 136)
#define SMEM_BYTES (SMEM_WORDS * 4)

__device__ __forceinline__ void quarter_bar(int Q) {
    asm volatile("bar.sync %0, 64;" :: "r"(Q + 1) : "memory");
}

__device__ __forceinline__ void transform64(float* __restrict__ d,
                                            const float4* __restrict__ Uy4,
                                            const float4* __restrict__ Ux4)
{
    // uy pass: 8 contiguous groups (x fixed)
#pragma unroll
    for (int x = 0; x < 8; x++) {
        float v[8];
#pragma unroll
        for (int k = 0; k < 8; k++) v[k] = d[x * 8 + k];
#pragma unroll
        for (int yo = 0; yo < 8; yo++) {
            const float4 ua = Uy4[yo * 2], ub = Uy4[yo * 2 + 1];
            float a =      ua.x * v[0];
            a = fmaf(ua.y, v[1], a);
            a = fmaf(ua.z, v[2], a);
            a = fmaf(ua.w, v[3], a);
            a = fmaf(ub.x, v[4], a);
            a = fmaf(ub.y, v[5], a);
            a = fmaf(ub.z, v[6], a);
            a = fmaf(ub.w, v[7], a);
            d[x * 8 + yo] = a;
        }
    }
    // ux pass: stride-8 groups (y fixed)
#pragma unroll
    for (int y = 0; y < 8; y++) {
        float v[8];
#pragma unroll
        for (int k = 0; k < 8; k++) v[k] = d[k * 8 + y];
#pragma unroll
        for (int xo = 0; xo < 8; xo++) {
            const float4 ua = Ux4[xo * 2], ub = Ux4[xo * 2 + 1];
            float a =      ua.x * v[0];
            a = fmaf(ua.y, v[1], a);
            a = fmaf(ua.z, v[2], a);
            a = fmaf(ua.w, v[3], a);
            a = fmaf(ub.x, v[4], a);
            a = fmaf(ub.y, v[5], a);
            a = fmaf(ub.z, v[6], a);
            a = fmaf(ub.w, v[7], a);
            d[xo * 8 + y] = a;
        }
    }
}

__global__ __launch_bounds__(NT, 2)
void qconv_kernel(const float* __restrict__ rho,
                  const float* __restrict__ gux,
                  const float* __restrict__ guy,
                  const float* __restrict__ guc,
                  float* __restrict__ out)
{
    extern __shared__ float sm[];
    float* A = sm;                        // 128 x 132

    const int tid  = threadIdx.x;
    const int Q    = tid >> 6;            // quarter 0..3
    const int qtid = tid & 63;
    const int H    = Q >> 1;              // left-channel block
    const int h    = Q & 1;               // right-half block
    float* sU = sm + A_WORDS + Q * 136;   // per-quarter U copy

    const int b = blockIdx.x;

    // ---- per-quarter init of U + wc (inside quarter barrier domain) ----
    sU[qtid]      = guy[qtid];
    sU[64 + qtid] = gux[qtid];
    if (qtid < 8)                          // i = c'*2 + c
        sU[128 + qtid] = guc[(qtid >> 1) * 4 + (qtid & 1) + 2];

    // ---- P1 (quarter): load rho rows [H*64,+64) x cols [h*64,+64) ----
    {
        const float4* src = (const float4*)(rho + (long)b * 16384);
#pragma unroll
        for (int i = 0; i < 16; i++) {
            const int idx = qtid + i * 64;       // 0..1023 float4s of the quarter
            const int seg = idx >> 4;            // row within block, 0..63
            const int f4  = idx & 15;            // float4 within 64-col half
            const float4 v = src[(H * 64 + seg) * 32 + h * 16 + f4];
            *(float4*)(A + (H * 64 + seg) * RS + h * 64 + f4 * 4) = v;
        }
    }
    quarter_bar(Q);

    const float4* Uy4 = (const float4*)sU;
    const float4* Ux4 = (const float4*)(sU + 64);

    // ---- P2 (quarter): right-side transform, row r of H block, h-half ----
    {
        const int r = H * 64 + qtid;
        float* base = A + r * RS + h * 64;
        float d[64];
#pragma unroll
        for (int i = 0; i < 16; i++) {
            const float4 v = *(const float4*)(base + 4 * i);
            d[4 * i] = v.x; d[4 * i + 1] = v.y; d[4 * i + 2] = v.z; d[4 * i + 3] = v.w;
        }
        transform64(d, Uy4, Ux4);
#pragma unroll
        for (int i = 0; i < 16; i++)
            *(float4*)(base + 4 * i) =
                make_float4(d[4 * i], d[4 * i + 1], d[4 * i + 2], d[4 * i + 3]);
    }
    quarter_bar(Q);

    // ---- P3 (quarter): left-side transform, column c = h*64+qtid, block H ----
    // Read-set == write-set per thread; no barrier between load and store.
    {
        float* base = A + (H * 64) * RS + h * 64 + qtid;
        float d[64];
#pragma unroll
        for (int i = 0; i < 64; i++) d[i] = base[i * RS];   // lanes stride-1
        transform64(d, Uy4, Ux4);
#pragma unroll
        for (int i = 0; i < 64; i++) base[i * RS] = d[i];
    }
    __syncthreads();

    // ---- P4: fused channel expansion on both sides + coalesced store ----
    float wc[8];
    {
        const float* wsrc = sm + A_WORDS + 128;   // quarter-0 copy (post-sync)
#pragma unroll
        for (int i = 0; i < 8; i++) wc[i] = wsrc[i];
    }

    float4* outb = (float4*)(out + (long)b * 65536);
    const float4* Af = (const float4*)A;          // row stride 33 float4

#pragma unroll
    for (int it = 0; it < 4; it++) {
        const int item = tid + it * NT;
        const int irv = item & 15;                // right pixel / 4
        const int il  = item >> 4;                // left pixel, 0..63

        const float4 m00 = Af[il * 33 + irv];              // cl=0, cr=0
        const float4 m01 = Af[il * 33 + 16 + irv];         // cl=0, cr=1
        const float4 m10 = Af[(64 + il) * 33 + irv];       // cl=1, cr=0
        const float4 m11 = Af[(64 + il) * 33 + 16 + irv];  // cl=1, cr=1

#pragma unroll
        for (int cpr = 0; cpr < 4; cpr++) {
            const float w0 = wc[cpr * 2], w1 = wc[cpr * 2 + 1];
            float4 t0, t1;
            t0.x = fmaf(w1, m01.x, w0 * m00.x);
            t0.y = fmaf(w1, m01.y, w0 * m00.y);
            t0.z = fmaf(w1, m01.z, w0 * m00.z);
            t0.w = fmaf(w1, m01.w, w0 * m00.w);
            t1.x = fmaf(w1, m11.x, w0 * m10.x);
            t1.y = fmaf(w1, m11.y, w0 * m10.y);
            t1.z = fmaf(w1, m11.z, w0 * m10.z);
            t1.w = fmaf(w1, m11.w, w0 * m10.w);
#pragma unroll
            for (int cpl = 0; cpl < 4; cpl++) {
                const float v0 = wc[cpl * 2], v1 = wc[cpl * 2 + 1];
                float4 o;
                o.x = fmaf(v1, t1.x, v0 * t0.x);
                o.y = fmaf(v1, t1.y, v0 * t0.y);
                o.z = fmaf(v1, t1.z, v0 * t0.z);
                o.w = fmaf(v1, t1.w, v0 * t0.w);
                outb[(cpl * 64 + il) * 64 + cpr * 16 + irv] = o;
            }
        }
    }
}

extern "C" void kernel_launch(void* const* d_in, const int* in_sizes, int n_in,
                              void* d_out, int out_size)
{
    const float* rho = (const float*)d_in[0];
    const float* ux  = (const float*)d_in[1];
    const float* uy  = (const float*)d_in[2];
    const float* uc  = (const float*)d_in[3];
    float* out = (float*)d_out;

    const int B = in_sizes[0] / 16384;

    cudaFuncSetAttribute(qconv_kernel,
                         cudaFuncAttributeMaxDynamicSharedMemorySize, SMEM_BYTES);
    qconv_kernel<<<B, NT, SMEM_BYTES>>>(rho, ux, uy, uc, out);
}